// round 16
// baseline (speedup 1.0000x reference)
#include <cuda_runtime.h>
#include <cuda_bf16.h>
#include <stdint.h>
#include <math.h>

#define S_   4096
#define E_   128
#define H_   256
#define NE_  4
#define NH_  4
#define HD_  64
#define FF_  2048
#define NL_  2
#define V_   10000
#define EPS_ 1e-5f
#define SCALE_ 0.125f   /* 1/sqrt(64) */
#define KVSPLIT 2

typedef __nv_bfloat16 bf16;

// ---------------- scratch (device globals; allocation-free) ----------------
__device__ float g_h  [S_ * H_];
__device__ float g_y  [S_ * H_];
__device__ float g_e0 [2 * S_ * H_];              // expert z-batch / residual temp
__device__ float g_po [KVSPLIT * S_ * H_];        // attn partial outputs
__device__ float g_ml [KVSPLIT * NH_ * S_ * 2];   // (m, l) per row per split
__device__ float g_vals[S_ * 2];
__device__ int   g_sel[4];                        // double-buffered expert pair

__device__ bf16 g_hbf [S_ * H_];
__device__ bf16 g_ybf [S_ * H_];
__device__ bf16 g_qkvbf[S_ * 3 * H_];
__device__ bf16 g_abf [S_ * H_];
__device__ bf16 g_ffbf[S_ * FF_];
__device__ bf16 g_fcbf[S_ * H_];
__device__ bf16 g_logbf[S_ * V_];

// bf16 weight mirrors
__device__ bf16 g_w_attn_in [NL_ * 3 * H_ * H_];
__device__ bf16 g_w_attn_out[NL_ * H_ * H_];
__device__ bf16 g_w_ff1     [NL_ * FF_ * H_];
__device__ bf16 g_w_ff2     [NL_ * H_ * FF_];
__device__ bf16 g_w_fc      [H_ * H_];
__device__ bf16 g_w_out     [V_ * H_];
__device__ bf16 g_w_moe0    [NE_ * H_ * E_];
__device__ bf16 g_w_moe1    [NE_ * H_ * H_];
__device__ bf16 g_w_moe2    [NE_ * H_ * H_];

// ---------------- batched fp32 -> bf16 convert ----------------
struct F2BFJobs {
    const float* src[9];
    bf16*        dst[9];
    int          off4[10];
};

__global__ void f2bf_multi(F2BFJobs j) {
    int i = blockIdx.x * blockDim.x + threadIdx.x;
    if (i >= j.off4[9]) return;
    int s = 0;
    #pragma unroll
    for (int k = 1; k < 9; k++) s += (i >= j.off4[k]);
    int local = (i - j.off4[s]) * 4;
    float4 v = *(const float4*)(j.src[s] + local);
    __nv_bfloat162 p0 = __float22bfloat162_rn(make_float2(v.x, v.y));
    __nv_bfloat162 p1 = __float22bfloat162_rn(make_float2(v.z, v.w));
    *(__nv_bfloat162*)(j.dst[s] + local)     = p0;
    *(__nv_bfloat162*)(j.dst[s] + local + 2) = p1;
}

// ---------------- embed gather (dual write) ----------------
__global__ void embed_kernel(const int* __restrict__ x, const float* __restrict__ emb,
                             float* __restrict__ out, bf16* __restrict__ outb) {
    int s = blockIdx.x;
    int d = threadIdx.x;           // E_ = 128 threads
    float v = emb[(long)x[s] * E_ + d];
    out[s * E_ + d]  = v;
    outb[s * E_ + d] = __float2bfloat16_rn(v);
}

// ---------------- MoE gate (standalone, block 0) ----------------
__global__ void gate_kernel(const float* __restrict__ x, int din,
                            const float* __restrict__ gw, const float* __restrict__ gb,
                            float* __restrict__ vals, int* __restrict__ sel) {
    int gtid = blockIdx.x * blockDim.x + threadIdx.x;
    int tok  = gtid >> 5;
    int lane = gtid & 31;
    if (tok >= S_) return;
    const float* xr = x + (long)tok * din;
    float p0 = 0.f, p1 = 0.f, p2 = 0.f, p3 = 0.f;
    for (int d = lane; d < din; d += 32) {
        float xv = xr[d];
        p0 += xv * gw[0 * din + d];
        p1 += xv * gw[1 * din + d];
        p2 += xv * gw[2 * din + d];
        p3 += xv * gw[3 * din + d];
    }
    #pragma unroll
    for (int o = 16; o > 0; o >>= 1) {
        p0 += __shfl_xor_sync(0xffffffffu, p0, o);
        p1 += __shfl_xor_sync(0xffffffffu, p1, o);
        p2 += __shfl_xor_sync(0xffffffffu, p2, o);
        p3 += __shfl_xor_sync(0xffffffffu, p3, o);
    }
    if (lane == 0) {
        float sc[4] = { p0 + gb[0], p1 + gb[1], p2 + gb[2], p3 + gb[3] };
        float m = fmaxf(fmaxf(sc[0], sc[1]), fmaxf(sc[2], sc[3]));
        float e[4]; float sum = 0.f;
        #pragma unroll
        for (int i = 0; i < 4; i++) { e[i] = __expf(sc[i] - m); sum += e[i]; }
        float inv = 1.f / sum;
        #pragma unroll
        for (int i = 0; i < 4; i++) e[i] *= inv;
        int i0 = 0;
        #pragma unroll
        for (int i = 1; i < 4; i++) if (e[i] > e[i0]) i0 = i;
        int i1 = -1;
        #pragma unroll
        for (int i = 0; i < 4; i++) {
            if (i == i0) continue;
            if (i1 < 0 || e[i] > e[i1]) i1 = i;
        }
        vals[tok * 2 + 0] = e[i0];
        vals[tok * 2 + 1] = e[i1];
        if (tok == 0) { sel[0] = i0; sel[1] = i1; }
    }
}

// ---------------- fused MoE combine + next-block gate ----------------
// warp per token: combine expert outputs (block i) AND compute gate scores for
// block i+1 on the combined activation. Math bit-identical to separate kernels.
__global__ void combine_gate(const float* __restrict__ e0, const float* __restrict__ e1,
                             const float* __restrict__ eb, const float* __restrict__ vals,
                             const int* __restrict__ sel_in,
                             const float* __restrict__ gw, const float* __restrict__ gb,
                             float* __restrict__ out, bf16* __restrict__ outb,
                             float* __restrict__ vals_out, int* __restrict__ sel_out) {
    int gtid = blockIdx.x * blockDim.x + threadIdx.x;
    int tok  = gtid >> 5;
    int lane = gtid & 31;
    if (tok >= S_) return;
    int s0 = sel_in[0], s1 = sel_in[1];
    float v0 = vals[tok * 2], v1 = vals[tok * 2 + 1];
    float p0 = 0.f, p1 = 0.f, p2 = 0.f, p3 = 0.f;
    #pragma unroll
    for (int k = 0; k < H_ / 32; k++) {
        int d = lane + k * 32;
        long i = (long)tok * H_ + d;
        float c = v0 * (e0[i] + eb[s0 * H_ + d]) + v1 * (e1[i] + eb[s1 * H_ + d]);
        out[i]  = c;
        outb[i] = __float2bfloat16_rn(c);
        p0 += c * gw[0 * H_ + d];
        p1 += c * gw[1 * H_ + d];
        p2 += c * gw[2 * H_ + d];
        p3 += c * gw[3 * H_ + d];
    }
    #pragma unroll
    for (int o = 16; o > 0; o >>= 1) {
        p0 += __shfl_xor_sync(0xffffffffu, p0, o);
        p1 += __shfl_xor_sync(0xffffffffu, p1, o);
        p2 += __shfl_xor_sync(0xffffffffu, p2, o);
        p3 += __shfl_xor_sync(0xffffffffu, p3, o);
    }
    if (lane == 0) {
        float sc[4] = { p0 + gb[0], p1 + gb[1], p2 + gb[2], p3 + gb[3] };
        float m = fmaxf(fmaxf(sc[0], sc[1]), fmaxf(sc[2], sc[3]));
        float e[4]; float sum = 0.f;
        #pragma unroll
        for (int i = 0; i < 4; i++) { e[i] = __expf(sc[i] - m); sum += e[i]; }
        float inv = 1.f / sum;
        #pragma unroll
        for (int i = 0; i < 4; i++) e[i] *= inv;
        int i0 = 0;
        #pragma unroll
        for (int i = 1; i < 4; i++) if (e[i] > e[i0]) i0 = i;
        int i1 = -1;
        #pragma unroll
        for (int i = 0; i < 4; i++) {
            if (i == i0) continue;
            if (i1 < 0 || e[i] > e[i1]) i1 = i;
        }
        vals_out[tok * 2 + 0] = e[i0];
        vals_out[tok * 2 + 1] = e[i1];
        if (tok == 0) { sel_out[0] = i0; sel_out[1] = i1; }
    }
}

// ---------------- MoE combine (final block, dual write, x2 vectorized) ----------------
__global__ void moe_combine(const float* __restrict__ e0, const float* __restrict__ e1,
                            const float* __restrict__ eb, const float* __restrict__ vals,
                            const int* __restrict__ sel, float* __restrict__ out,
                            bf16* __restrict__ outb) {
    long p = (long)blockIdx.x * blockDim.x + threadIdx.x;
    if (p >= (long)S_ * H_ / 2) return;
    long i = p * 2;
    int s = (int)(i / H_);
    int h = (int)(i % H_);
    float2 b0 = *(const float2*)(eb + sel[0] * H_ + h);
    float2 b1 = *(const float2*)(eb + sel[1] * H_ + h);
    float2 a  = *(const float2*)(e0 + i);
    float2 b  = *(const float2*)(e1 + i);
    float v0s = vals[s * 2], v1s = vals[s * 2 + 1];
    float r0 = v0s * (a.x + b0.x) + v1s * (b.x + b1.x);
    float r1 = v0s * (a.y + b0.y) + v1s * (b.y + b1.y);
    *(float2*)(out + i) = make_float2(r0, r1);
    __nv_bfloat162 pk = __float22bfloat162_rn(make_float2(r0, r1));
    *(__nv_bfloat162*)(outb + i) = pk;
}

#define MMA_BF16(ACC, A0, A1, A2, A3, B0, B1)                                  \
    asm volatile(                                                              \
        "mma.sync.aligned.m16n8k16.row.col.f32.bf16.bf16.f32 "                 \
        "{%0,%1,%2,%3}, {%4,%5,%6,%7}, {%8,%9}, {%0,%1,%2,%3};\n"              \
        : "+f"((ACC)[0]), "+f"((ACC)[1]), "+f"((ACC)[2]), "+f"((ACC)[3])       \
        : "r"(A0), "r"(A1), "r"(A2), "r"(A3), "r"(B0), "r"(B1))

static __device__ __forceinline__ unsigned packbf(float x, float y) {
    __nv_bfloat162 p = __float22bfloat162_rn(make_float2(x, y));
    return *(unsigned*)&p;
}

static __device__ __forceinline__ void cp16(unsigned dst, const void* src, int sz) {
    asm volatile("cp.async.ca.shared.global [%0], [%1], 16, %2;\n"
                 :: "r"(dst), "l"(src), "r"(sz));
}

// ---------------- bf16 GEMM, cp.async 3-stage pipeline, BK=64 ----------------
template <int BN>
__global__ __launch_bounds__(256, 2)
void gemm_bf(const bf16* __restrict__ A, const bf16* __restrict__ B,
             const float* __restrict__ bias, float* __restrict__ C, bf16* __restrict__ Cb,
             int M, int N, int K, int lda, int ldb, int ldc,
             long batchC, int do_relu, const int* __restrict__ sel, long selStride) {
    constexpr int BM = 128, BK = 64, PAD = 8;
    constexpr int RS = BK + PAD;
    constexpr int ROWS = BM + BN;
    constexpr int NT = BN / 16;
    extern __shared__ __align__(16) bf16 sm[];

    if (sel) B += (long)sel[blockIdx.z] * selStride;
    long zoff = (long)blockIdx.z * batchC;

    int bm = blockIdx.y * BM;
    int bn = blockIdx.x * BN;
    int tid  = threadIdx.x;
    int lane = tid & 31;
    int wid  = tid >> 5;
    int warpM = (wid & 3) * 32;
    int warpN = (wid >> 2) * (BN / 2);
    unsigned sbase = (unsigned)__cvta_generic_to_shared(sm);

    auto issue = [&](int stage, int k0) {
        #pragma unroll
        for (int t = 0; t < BM * 8 / 256; t++) {
            int idx = tid + t * 256;
            int row = idx >> 3, c = idx & 7;
            const void* src = A + (long)(bm + row) * lda + k0 + c * 8;
            unsigned dst = sbase + (unsigned)(((stage * ROWS + row) * RS + c * 8) * 2);
            cp16(dst, src, 16);
        }
        #pragma unroll
        for (int t = 0; t < BN * 8 / 256; t++) {
            int idx = tid + t * 256;
            int row = idx >> 3, c = idx & 7;
            int gn = bn + row;
            const void* src = B + (long)(gn < N ? gn : 0) * ldb + k0 + c * 8;
            unsigned dst = sbase + (unsigned)(((stage * ROWS + BM + row) * RS + c * 8) * 2);
            cp16(dst, src, gn < N ? 16 : 0);
        }
        asm volatile("cp.async.commit_group;\n");
    };

    float acc[2][NT][4];
    #pragma unroll
    for (int mt = 0; mt < 2; mt++)
        #pragma unroll
        for (int nt = 0; nt < NT; nt++)
            #pragma unroll
            for (int r = 0; r < 4; r++) acc[mt][nt][r] = 0.f;

    int g = lane >> 2;
    int q = lane & 3;
    int ntiles = K / BK;

    auto compute = [&](int stage) {
        const bf16* As = sm + stage * ROWS * RS;
        const bf16* Bs = As + BM * RS;
        #pragma unroll
        for (int ks = 0; ks < BK; ks += 16) {
            unsigned a[2][4], b[NT][2];
            int ac = ks + q * 2;
            #pragma unroll
            for (int mt = 0; mt < 2; mt++) {
                int r = warpM + mt * 16 + g;
                a[mt][0] = *(const unsigned*)&As[r * RS + ac];
                a[mt][1] = *(const unsigned*)&As[(r + 8) * RS + ac];
                a[mt][2] = *(const unsigned*)&As[r * RS + ac + 8];
                a[mt][3] = *(const unsigned*)&As[(r + 8) * RS + ac + 8];
            }
            #pragma unroll
            for (int nt = 0; nt < NT; nt++) {
                int nr = warpN + nt * 8 + g;
                b[nt][0] = *(const unsigned*)&Bs[nr * RS + ac];
                b[nt][1] = *(const unsigned*)&Bs[nr * RS + ac + 8];
            }
            #pragma unroll
            for (int mt = 0; mt < 2; mt++)
                #pragma unroll
                for (int nt = 0; nt < NT; nt++)
                    MMA_BF16(acc[mt][nt], a[mt][0], a[mt][1], a[mt][2], a[mt][3],
                             b[nt][0], b[nt][1]);
        }
    };

    issue(0, 0);
    if (ntiles > 1) issue(1, BK);
    for (int t = 0; t < ntiles; t++) {
        if (t == ntiles - 1)
            asm volatile("cp.async.wait_group 0;\n");
        else
            asm volatile("cp.async.wait_group 1;\n");
        __syncthreads();
        if (t + 2 < ntiles) issue((t + 2) % 3, (t + 2) * BK);
        compute(t % 3);
    }

    #pragma unroll
    for (int mt = 0; mt < 2; mt++) {
        int row0 = bm + warpM + mt * 16 + g;
        #pragma unroll
        for (int nt = 0; nt < NT; nt++) {
            int col = bn + warpN + nt * 8 + q * 2;
            if (col >= N) continue;
            float b0 = bias ? bias[col]     : 0.f;
            float b1 = bias ? bias[col + 1] : 0.f;
            float v00 = acc[mt][nt][0] + b0;
            float v01 = acc[mt][nt][1] + b1;
            float v10 = acc[mt][nt][2] + b0;
            float v11 = acc[mt][nt][3] + b1;
            if (do_relu) {
                v00 = fmaxf(v00, 0.f); v01 = fmaxf(v01, 0.f);
                v10 = fmaxf(v10, 0.f); v11 = fmaxf(v11, 0.f);
            }
            if (Cb) {
                *(unsigned*)(Cb + zoff + (long)row0 * ldc + col)       = packbf(v00, v01);
                *(unsigned*)(Cb + zoff + (long)(row0 + 8) * ldc + col) = packbf(v10, v11);
            } else {
                *(float2*)(C + zoff + (long)row0 * ldc + col)       = make_float2(v00, v01);
                *(float2*)(C + zoff + (long)(row0 + 8) * ldc + col) = make_float2(v10, v11);
            }
        }
    }
}

// ---------------- split-KV flash attention, smem double-buffered K/V ----------------
#define FL_SMEM (128 * 72 + 2 * 64 * 72 + 2 * 64 * 72)
__global__ __launch_bounds__(256)
void flash_attn(const bf16* __restrict__ qkv, float* __restrict__ po,
                float* __restrict__ ml) {
    constexpr int BM = 128, BN = 64, RSF = 72;
    constexpr int JT = S_ / BN / KVSPLIT;
    extern __shared__ __align__(16) bf16 smf[];
    bf16* Qs    = smf;
    bf16* Kbase = smf + 128 * RSF;
    bf16* Vbase = Kbase + 2 * 64 * RSF;

    int h  = blockIdx.y;
    int z  = blockIdx.z;
    int bm = blockIdx.x * BM;
    int tid = threadIdx.x;
    int lane = tid & 31;
    int w = tid >> 5;
    int g = lane >> 2;
    int q = lane & 3;

    const bf16* Qp = qkv + h * HD_;
    const bf16* Kp = qkv + H_ + h * HD_;
    const bf16* Vp = qkv + 2 * H_ + h * HD_;

    int skey[2], sc[2];
    #pragma unroll
    for (int i = 0; i < 2; i++) {
        int idx = tid + i * 256;
        skey[i] = idx >> 3;
        sc[i]   = idx & 7;
    }

    #pragma unroll
    for (int i = 0; i < 4; i++) {
        int idx = tid + i * 256;
        int row = idx >> 3;
        int c   = idx & 7;
        uint4 v = *(const uint4*)(Qp + (long)(bm + row) * (3 * H_) + c * 8);
        *(uint4*)&Qs[row * RSF + c * 8] = v;
    }

    float m0 = -1e30f, m1 = -1e30f, l0 = 0.f, l1 = 0.f;
    float out[8][4];
    #pragma unroll
    for (int ot = 0; ot < 8; ot++)
        #pragma unroll
        for (int r = 0; r < 4; r++) out[ot][r] = 0.f;

    int rowA = w * 16 + g;

    long jbase = (long)z * JT * BN;
    uint4 kreg[2], vreg[2];
    #pragma unroll
    for (int i = 0; i < 2; i++) {
        kreg[i] = *(const uint4*)(Kp + (jbase + skey[i]) * (3 * H_) + sc[i] * 8);
        vreg[i] = *(const uint4*)(Vp + (jbase + skey[i]) * (3 * H_) + sc[i] * 8);
    }

    for (int jj = 0; jj < JT; jj++) {
        bf16* Ks = Kbase + (jj & 1) * 64 * RSF;
        bf16* Vs = Vbase + (jj & 1) * 64 * RSF;
        #pragma unroll
        for (int i = 0; i < 2; i++) {
            *(uint4*)&Ks[skey[i] * RSF + sc[i] * 8] = kreg[i];
            __nv_bfloat162 p0 = *(__nv_bfloat162*)&vreg[i].x;
            __nv_bfloat162 p1 = *(__nv_bfloat162*)&vreg[i].y;
            __nv_bfloat162 p2 = *(__nv_bfloat162*)&vreg[i].z;
            __nv_bfloat162 p3 = *(__nv_bfloat162*)&vreg[i].w;
            int d0 = sc[i] * 8;
            int key = skey[i];
            Vs[(d0 + 0) * RSF + key] = p0.x; Vs[(d0 + 1) * RSF + key] = p0.y;
            Vs[(d0 + 2) * RSF + key] = p1.x; Vs[(d0 + 3) * RSF + key] = p1.y;
            Vs[(d0 + 4) * RSF + key] = p2.x; Vs[(d0 + 5) * RSF + key] = p2.y;
            Vs[(d0 + 6) * RSF + key] = p3.x; Vs[(d0 + 7) * RSF + key] = p3.y;
        }
        __syncthreads();

        if (jj + 1 < JT) {
            long base = jbase + (long)(jj + 1) * BN;
            #pragma unroll
            for (int i = 0; i < 2; i++) {
                kreg[i] = *(const uint4*)(Kp + (base + skey[i]) * (3 * H_) + sc[i] * 8);
                vreg[i] = *(const uint4*)(Vp + (base + skey[i]) * (3 * H_) + sc[i] * 8);
            }
        }

        float acc[8][4];
        #pragma unroll
        for (int nt = 0; nt < 8; nt++)
            #pragma unroll
            for (int r = 0; r < 4; r++) acc[nt][r] = 0.f;
        #pragma unroll
        for (int kc = 0; kc < 4; kc++) {
            int ac = kc * 16 + q * 2;
            unsigned a0 = *(const unsigned*)&Qs[rowA * RSF + ac];
            unsigned a1 = *(const unsigned*)&Qs[(rowA + 8) * RSF + ac];
            unsigned a2 = *(const unsigned*)&Qs[rowA * RSF + ac + 8];
            unsigned a3 = *(const unsigned*)&Qs[(rowA + 8) * RSF + ac + 8];
            #pragma unroll
            for (int nt = 0; nt < 8; nt++) {
                unsigned b0 = *(const unsigned*)&Ks[(nt * 8 + g) * RSF + ac];
                unsigned b1 = *(const unsigned*)&Ks[(nt * 8 + g) * RSF + ac + 8];
                MMA_BF16(acc[nt], a0, a1, a2, a3, b0, b1);
            }
        }

        float tm0 = -1e30f, tm1 = -1e30f;
        #pragma unroll
        for (int nt = 0; nt < 8; nt++) {
            acc[nt][0] *= SCALE_; acc[nt][1] *= SCALE_;
            acc[nt][2] *= SCALE_; acc[nt][3] *= SCALE_;
            tm0 = fmaxf(tm0, fmaxf(acc[nt][0], acc[nt][1]));
            tm1 = fmaxf(tm1, fmaxf(acc[nt][2], acc[nt][3]));
        }
        tm0 = fmaxf(tm0, __shfl_xor_sync(0xffffffffu, tm0, 1));
        tm0 = fmaxf(tm0, __shfl_xor_sync(0xffffffffu, tm0, 2));
        tm1 = fmaxf(tm1, __shfl_xor_sync(0xffffffffu, tm1, 1));
        tm1 = fmaxf(tm1, __shfl_xor_sync(0xffffffffu, tm1, 2));
        float mn0 = fmaxf(m0, tm0), mn1 = fmaxf(m1, tm1);
        float corr0 = __expf(m0 - mn0), corr1 = __expf(m1 - mn1);
        float s0 = 0.f, s1 = 0.f;
        #pragma unroll
        for (int nt = 0; nt < 8; nt++) {
            acc[nt][0] = __expf(acc[nt][0] - mn0);
            acc[nt][1] = __expf(acc[nt][1] - mn0);
            acc[nt][2] = __expf(acc[nt][2] - mn1);
            acc[nt][3] = __expf(acc[nt][3] - mn1);
            s0 += acc[nt][0] + acc[nt][1];
            s1 += acc[nt][2] + acc[nt][3];
        }
        m0 = mn0; m1 = mn1;
        l0 = l0 * corr0 + s0;
        l1 = l1 * corr1 + s1;
        #pragma unroll
        for (int ot = 0; ot < 8; ot++) {
            out[ot][0] *= corr0; out[ot][1] *= corr0;
            out[ot][2] *= corr1; out[ot][3] *= corr1;
        }

        #pragma unroll
        for (int kc = 0; kc < 4; kc++) {
            unsigned a0 = packbf(acc[2 * kc][0],     acc[2 * kc][1]);
            unsigned a1 = packbf(acc[2 * kc][2],     acc[2 * kc][3]);
            unsigned a2 = packbf(acc[2 * kc + 1][0], acc[2 * kc + 1][1]);
            unsigned a3 = packbf(acc[2 * kc + 1][2], acc[2 * kc + 1][3]);
            int kb = kc * 16 + q * 2;
            #pragma unroll
            for (int ot = 0; ot < 8; ot++) {
                unsigned b0 = *(const unsigned*)&Vs[(ot * 8 + g) * RSF + kb];
                unsigned b1 = *(const unsigned*)&Vs[(ot * 8 + g) * RSF + kb + 8];
                MMA_BF16(out[ot], a0, a1, a2, a3, b0, b1);
            }
        }
    }

    l0 += __shfl_xor_sync(0xffffffffu, l0, 1);
    l0 += __shfl_xor_sync(0xffffffffu, l0, 2);
    l1 += __shfl_xor_sync(0xffffffffu, l1, 1);
    l1 += __shfl_xor_sync(0xffffffffu, l1, 2);
    int row0 = bm + w * 16 + g;
    float* dst = po + (long)z * S_ * H_;
    #pragma unroll
    for (int ot = 0; ot < 8; ot++) {
        int col = h * HD_ + ot * 8 + q * 2;
        *(float2*)(dst + (long)row0 * H_ + col)       = make_float2(out[ot][0], out[ot][1]);
        *(float2*)(dst + (long)(row0 + 8) * H_ + col) = make_float2(out[ot][2], out[ot][3]);
    }
    if (q == 0) {
        long mlbase = ((long)z * NH_ + h) * S_;
        ml[(mlbase + row0) * 2 + 0] = m0;
        ml[(mlbase + row0) * 2 + 1] = l0;
        ml[(mlbase + row0 + 8) * 2 + 0] = m1;
        ml[(mlbase + row0 + 8) * 2 + 1] = l1;
    }
}

// ---------------- split-KV merge (x2 vectorized) ----------------
__global__ void attn_merge(const float* __restrict__ po, const float* __restrict__ ml,
                           bf16* __restrict__ o) {
    long p = (long)blockIdx.x * blockDim.x + threadIdx.x;
    if (p >= (long)S_ * H_ / 2) return;
    long i = p * 2;
    int s   = (int)(i / H_);
    int col = (int)(i % H_);
    int h   = col / HD_;
    float mz[KVSPLIT], lz[KVSPLIT];
    float m = -1e30f;
    #pragma unroll
    for (int z = 0; z < KVSPLIT; z++) {
        mz[z] = ml[(((long)z * NH_ + h) * S_ + s) * 2 + 0];
        lz[z] = ml[(((long)z * NH_ + h) * S_ + s) * 2 + 1];
        m = fmaxf(m, mz[z]);
    }
    float n0 = 0.f, n1 = 0.f, den = 0.f;
    #pragma unroll
    for (int z = 0; z < KVSPLIT; z++) {
        float c = __expf(mz[z] - m);
        float2 v = *(const float2*)(po + (long)z * S_ * H_ + i);
        n0 += v.x * c;
        n1 += v.y * c;
        den += lz[z] * c;
    }
    float inv = 1.f / den;
    __nv_bfloat162 pk = __float22bfloat162_rn(make_float2(n0 * inv, n1 * inv));
    *(__nv_bfloat162*)(o + i) = pk;
}

// ---------------- residual add + LayerNorm (warp-shuffle reductions) ----------------
__global__ void ln_kernel(float* __restrict__ h, const float* __restrict__ t,
                          const float* __restrict__ g, const float* __restrict__ b,
                          bf16* __restrict__ hb) {
    __shared__ float ws1[8], ws2[8];
    int s = blockIdx.x;
    int d = threadIdx.x;
    int lane = d & 31;
    int w = d >> 5;
    float v = h[s * H_ + d] + t[s * H_ + d];
    float sum = v;
    #pragma unroll
    for (int o = 16; o > 0; o >>= 1) sum += __shfl_xor_sync(0xffffffffu, sum, o);
    if (lane == 0) ws1[w] = sum;
    __syncthreads();
    float tot = ws1[0] + ws1[1] + ws1[2] + ws1[3] + ws1[4] + ws1[5] + ws1[6] + ws1[7];
    float m = tot * (1.f / H_);
    float c = v - m;
    float s2 = c * c;
    #pragma unroll
    for (int o = 16; o > 0; o >>= 1) s2 += __shfl_xor_sync(0xffffffffu, s2, o);
    if (lane == 0) ws2[w] = s2;
    __syncthreads();
    float tot2 = ws2[0] + ws2[1] + ws2[2] + ws2[3] + ws2[4] + ws2[5] + ws2[6] + ws2[7];
    float var = tot2 * (1.f / H_);
    float r = c * rsqrtf(var + EPS_) * g[d] + b[d];
    h[s * H_ + d]  = r;
    hb[s * H_ + d] = __float2bfloat16_rn(r);
}

// ---------------- final log_softmax: bf16x2 loads, fp32 out ----------------
__global__ void logsoftmax_kernel(const bf16* __restrict__ logits, float* __restrict__ out) {
    __shared__ float red[256];
    const bf16* p = logits + (long)blockIdx.x * V_;
    float* po = out + (long)blockIdx.x * V_;
    int t = threadIdx.x;
    float2 loc[20];                    // pairs: 256 thr x 20 = 5120 >= V/2 = 5000
    float m = -1e30f;
    #pragma unroll
    for (int i = 0; i < 20; i++) {
        int c2 = t + i * 256;
        if (c2 < V_ / 2) {
            __nv_bfloat162 v = *(const __nv_bfloat162*)(p + c2 * 2);
            loc[i] = make_float2(__bfloat162float(v.x), __bfloat162float(v.y));
        } else {
            loc[i] = make_float2(-1e30f, -1e30f);
        }
        m = fmaxf(m, fmaxf(loc[i].x, loc[i].y));
    }
    red[t] = m;
    __syncthreads();
    for (int o = 128; o > 0; o >>= 1) {
        if (t < o) red[t] = fmaxf(red[t], red[t + o]);
        __syncthreads();
    }
    m = red[0];
    __syncthreads();
    float sum = 0.f;
    #pragma unroll
    for (int i = 0; i < 20; i++) {
        int c2 = t + i * 256;
        if (c2 < V_ / 2)
            sum += __expf(loc[i].x - m) + __expf(loc[i].y - m);
    }
    red[t] = sum;
    __syncthreads();
    for (int o = 128; o > 0; o >>= 1) {
        if (t < o) red[t] += red[t + o];
        __syncthreads();
    }
    float lse = m + __logf(red[0]);
    #pragma unroll
    for (int i = 0; i < 20; i++) {
        int c2 = t + i * 256;
        if (c2 < V_ / 2)
            *(float2*)(po + c2 * 2) = make_float2(loc[i].x - lse, loc[i].y - lse);
    }
}

// ---------------- host side ----------------
static inline void gemm(const bf16* A, const bf16* B, const float* bias,
                        float* C, bf16* Cb,
                        int M, int N, int K, int lda, int ldb, int ldc,
                        int relu,
                        int Z = 1, long batchC = 0,
                        const int* sel = nullptr, long selStride = 0) {
    if (N >= 768) {
        constexpr int SMEM128 = 3 * (128 + 128) * 72 * 2;
        cudaFuncSetAttribute(gemm_bf<128>, cudaFuncAttributeMaxDynamicSharedMemorySize,
                             SMEM128);
        dim3 grid((N + 127) / 128, M / 128, Z);
        gemm_bf<128><<<grid, 256, SMEM128>>>(A, B, bias, C, Cb, M, N, K, lda, ldb, ldc,
                                             batchC, relu, sel, selStride);
    } else {
        constexpr int SMEM64 = 3 * (128 + 64) * 72 * 2;
        cudaFuncSetAttribute(gemm_bf<64>, cudaFuncAttributeMaxDynamicSharedMemorySize,
                             SMEM64);
        dim3 grid((N + 63) / 64, M / 128, Z);
        gemm_bf<64><<<grid, 256, SMEM64>>>(A, B, bias, C, Cb, M, N, K, lda, ldb, ldc,
                                           batchC, relu, sel, selStride);
    }
}

extern "C" void kernel_launch(void* const* d_in, const int* in_sizes, int n_in,
                              void* d_out, int out_size) {
    const int*   x         = (const int*)d_in[0];
    const float* emb       = (const float*)d_in[1];
    const float* moe_gw[3] = { (const float*)d_in[2], (const float*)d_in[6], (const float*)d_in[10] };
    const float* moe_gb[3] = { (const float*)d_in[3], (const float*)d_in[7], (const float*)d_in[11] };
    const float* moe_ew[3] = { (const float*)d_in[4], (const float*)d_in[8], (const float*)d_in[12] };
    const float* moe_eb[3] = { (const float*)d_in[5], (const float*)d_in[9], (const float*)d_in[13] };
    const float* attn_in_w  = (const float*)d_in[14];
    const float* attn_in_b  = (const float*)d_in[15];
    const float* attn_out_w = (const float*)d_in[16];
    const float* attn_out_b = (const float*)d_in[17];
    const float* ln1_g = (const float*)d_in[18];
    const float* ln1_b = (const float*)d_in[19];
    const float* ln2_g = (const float*)d_in[20];
    const float* ln2_b = (const float*)d_in[21];
    const float* ff1_w = (const float*)d_in[22];
    const float* ff1_b = (const float*)d_in[23];
    const float* ff2_w = (const float*)d_in[24];
    const float* ff2_b = (const float*)d_in[25];
    const float* fc_w  = (const float*)d_in[26];
    const float* fc_b  = (const float*)d_in[27];
    const float* out_w = (const float*)d_in[28];
    const float* out_b = (const float*)d_in[29];
    float* out = (float*)d_out;

    float *hbuf, *ybuf, *e0, *pob, *mlb, *vals;
    int* sel;
    bf16 *hbf, *ybf, *qkvbf, *abf, *ffbf, *fcbf, *logbf;
    bf16 *w_ain, *w_aout, *w_ff1, *w_ff2, *w_fc, *w_out, *w_m0, *w_m1, *w_m2;
    cudaGetSymbolAddress((void**)&hbuf, g_h);
    cudaGetSymbolAddress((void**)&ybuf, g_y);
    cudaGetSymbolAddress((void**)&e0,   g_e0);
    cudaGetSymbolAddress((void**)&pob,  g_po);
    cudaGetSymbolAddress((void**)&mlb,  g_ml);
    cudaGetSymbolAddress((void**)&vals, g_vals);
    cudaGetSymbolAddress((void**)&sel,  g_sel);
    cudaGetSymbolAddress((void**)&hbf,   g_hbf);
    cudaGetSymbolAddress((void**)&ybf,   g_ybf);
    cudaGetSymbolAddress((void**)&qkvbf, g_qkvbf);
    cudaGetSymbolAddress((void**)&abf,   g_abf);
    cudaGetSymbolAddress((void**)&ffbf,  g_ffbf);
    cudaGetSymbolAddress((void**)&fcbf,  g_fcbf);
    cudaGetSymbolAddress((void**)&logbf, g_logbf);
    cudaGetSymbolAddress((void**)&w_ain,  g_w_attn_in);
    cudaGetSymbolAddress((void**)&w_aout, g_w_attn_out);
    cudaGetSymbolAddress((void**)&w_ff1,  g_w_ff1);
    cudaGetSymbolAddress((void**)&w_ff2,  g_w_ff2);
    cudaGetSymbolAddress((void**)&w_fc,   g_w_fc);
    cudaGetSymbolAddress((void**)&w_out,  g_w_out);
    cudaGetSymbolAddress((void**)&w_m0,   g_w_moe0);
    cudaGetSymbolAddress((void**)&w_m1,   g_w_moe1);
    cudaGetSymbolAddress((void**)&w_m2,   g_w_moe2);

    int* sel_a = sel;
    int* sel_b = sel + 2;

    // 0) weight conversion — one batched launch
    {
        F2BFJobs j;
        const float* srcs[9] = { attn_in_w, attn_out_w, ff1_w, ff2_w, fc_w,
                                 out_w, moe_ew[0], moe_ew[1], moe_ew[2] };
        bf16* dsts[9] = { w_ain, w_aout, w_ff1, w_ff2, w_fc, w_out, w_m0, w_m1, w_m2 };
        int ns[9] = { NL_ * 3 * H_ * H_, NL_ * H_ * H_, NL_ * FF_ * H_, NL_ * H_ * FF_,
                      H_ * H_, V_ * H_, NE_ * H_ * E_, NE_ * H_ * H_, NE_ * H_ * H_ };
        int acc = 0;
        for (int i = 0; i < 9; i++) {
            j.src[i] = srcs[i];
            j.dst[i] = dsts[i];
            j.off4[i] = acc;
            acc += ns[i] / 4;
        }
        j.off4[9] = acc;
        f2bf_multi<<<(acc + 255) / 256, 256>>>(j);
    }

    // 1) embedding gather
    embed_kernel<<<S_, E_>>>(x, emb, hbuf, hbf);

    // 2) MoE chain: gate0 -> gemm0 -> [combine0+gate1] -> gemm1 -> [combine1+gate2]
    //    -> gemm2 -> combine2
    gate_kernel<<<(S_ * 32) / 256, 256>>>(hbuf, E_, moe_gw[0], moe_gb[0], vals, sel_a);
    gemm(hbf, w_m0, nullptr, e0, nullptr, S_, H_, E_, E_, E_, H_,
         0, 2, (long)S_ * H_, sel_a, (long)H_ * E_);
    combine_gate<<<(S_ * 32) / 256, 256>>>(e0, e0 + (long)S_ * H_, moe_eb[0], vals, sel_a,
                                           moe_gw[1], moe_gb[1], ybuf, ybf, vals, sel_b);
    gemm(ybf, w_m1, nullptr, e0, nullptr, S_, H_, H_, H_, H_, H_,
         0, 2, (long)S_ * H_, sel_b, (long)H_ * H_);
    combine_gate<<<(S_ * 32) / 256, 256>>>(e0, e0 + (long)S_ * H_, moe_eb[1], vals, sel_b,
                                           moe_gw[2], moe_gb[2], hbuf, hbf, vals, sel_a);
    gemm(hbf, w_m2, nullptr, e0, nullptr, S_, H_, H_, H_, H_, H_,
         0, 2, (long)S_ * H_, sel_a, (long)H_ * H_);
    moe_combine<<<(S_ * H_ / 2 + 255) / 256, 256>>>(e0, e0 + (long)S_ * H_, moe_eb[2],
                                                    vals, sel_a, ybuf, ybf);
    float* cur  = ybuf;
    bf16*  curb = ybf;

    // 3) transformer layers
    cudaFuncSetAttribute(flash_attn, cudaFuncAttributeMaxDynamicSharedMemorySize,
                         FL_SMEM * 2);
    for (int l = 0; l < NL_; l++) {
        gemm(curb, w_ain + (long)l * 3 * H_ * H_, attn_in_b + (long)l * 3 * H_,
             nullptr, qkvbf, S_, 3 * H_, H_, H_, H_, 3 * H_, 0);
        flash_attn<<<dim3(S_ / 128, NH_, KVSPLIT), 256, FL_SMEM * 2>>>(qkvbf, pob, mlb);
        attn_merge<<<(S_ * H_ / 2 + 255) / 256, 256>>>(pob, mlb, abf);
        gemm(abf, w_aout + (long)l * H_ * H_, attn_out_b + (long)l * H_,
             e0, nullptr, S_, H_, H_, H_, H_, H_, 0);
        ln_kernel<<<S_, H_>>>(cur, e0, ln1_g + l * H_, ln1_b + l * H_, curb);
        gemm(curb, w_ff1 + (long)l * FF_ * H_, ff1_b + (long)l * FF_,
             nullptr, ffbf, S_, FF_, H_, H_, H_, FF_, 1);
        gemm(ffbf, w_ff2 + (long)l * H_ * FF_, ff2_b + (long)l * H_,
             e0, nullptr, S_, H_, FF_, FF_, FF_, H_, 0);
        ln_kernel<<<S_, H_>>>(cur, e0, ln2_g + l * H_, ln2_b + l * H_, curb);
    }

    // 4) fc + vocab logits (bf16) + log_softmax (bf16 -> fp32 out)
    gemm(curb, w_fc, fc_b, nullptr, fcbf, S_, H_, H_, H_, H_, H_, 0);
    gemm(fcbf, w_out, out_b, nullptr, logbf, S_, V_, H_, H_, H_, V_, 0);
    logsoftmax_kernel<<<S_, 256>>>(logbf, out);
}

// round 17
// speedup vs baseline: 1.4825x; 1.4825x over previous
#include <cuda_runtime.h>
#include <cuda_bf16.h>
#include <stdint.h>
#include <math.h>

#define S_   4096
#define E_   128
#define H_   256
#define NE_  4
#define NH_  4
#define HD_  64
#define FF_  2048
#define NL_  2
#define V_   10000
#define EPS_ 1e-5f
#define SCALE_ 0.125f   /* 1/sqrt(64) */
#define KVSPLIT 2

typedef __nv_bfloat16 bf16;

// ---------------- scratch (device globals; allocation-free) ----------------
__device__ float g_h  [S_ * H_];
__device__ float g_y  [S_ * H_];
__device__ float g_e0 [2 * S_ * H_];              // expert z-batch / residual temp
__device__ float g_po [KVSPLIT * S_ * H_];        // attn partial outputs
__device__ float g_ml [KVSPLIT * NH_ * S_ * 2];   // (m, l) per row per split
__device__ float g_vals[S_ * 2];
__device__ int   g_sel[2];

__device__ bf16 g_hbf [S_ * H_];
__device__ bf16 g_ybf [S_ * H_];
__device__ bf16 g_qkvbf[S_ * 3 * H_];
__device__ bf16 g_abf [S_ * H_];
__device__ bf16 g_ffbf[S_ * FF_];
__device__ bf16 g_fcbf[S_ * H_];
__device__ bf16 g_logbf[S_ * V_];

// bf16 weight mirrors
__device__ bf16 g_w_attn_in [NL_ * 3 * H_ * H_];
__device__ bf16 g_w_attn_out[NL_ * H_ * H_];
__device__ bf16 g_w_ff1     [NL_ * FF_ * H_];
__device__ bf16 g_w_ff2     [NL_ * H_ * FF_];
__device__ bf16 g_w_fc      [H_ * H_];
__device__ bf16 g_w_out     [V_ * H_];
__device__ bf16 g_w_moe0    [NE_ * H_ * E_];
__device__ bf16 g_w_moe1    [NE_ * H_ * H_];
__device__ bf16 g_w_moe2    [NE_ * H_ * H_];

// ---------------- batched fp32 -> bf16 convert ----------------
struct F2BFJobs {
    const float* src[9];
    bf16*        dst[9];
    int          off4[10];
};

__global__ void f2bf_multi(F2BFJobs j) {
    int i = blockIdx.x * blockDim.x + threadIdx.x;
    if (i >= j.off4[9]) return;
    int s = 0;
    #pragma unroll
    for (int k = 1; k < 9; k++) s += (i >= j.off4[k]);
    int local = (i - j.off4[s]) * 4;
    float4 v = *(const float4*)(j.src[s] + local);
    __nv_bfloat162 p0 = __float22bfloat162_rn(make_float2(v.x, v.y));
    __nv_bfloat162 p1 = __float22bfloat162_rn(make_float2(v.z, v.w));
    *(__nv_bfloat162*)(j.dst[s] + local)     = p0;
    *(__nv_bfloat162*)(j.dst[s] + local + 2) = p1;
}

// ---------------- embed gather (dual write) ----------------
__global__ void embed_kernel(const int* __restrict__ x, const float* __restrict__ emb,
                             float* __restrict__ out, bf16* __restrict__ outb) {
    int s = blockIdx.x;
    int d = threadIdx.x;           // E_ = 128 threads
    float v = emb[(long)x[s] * E_ + d];
    out[s * E_ + d]  = v;
    outb[s * E_ + d] = __float2bfloat16_rn(v);
}

// ---------------- MoE gate ----------------
__global__ void gate_kernel(const float* __restrict__ x, int din,
                            const float* __restrict__ gw, const float* __restrict__ gb,
                            float* __restrict__ vals, int* __restrict__ sel) {
    int gtid = blockIdx.x * blockDim.x + threadIdx.x;
    int tok  = gtid >> 5;
    int lane = gtid & 31;
    if (tok >= S_) return;
    const float* xr = x + (long)tok * din;
    float p0 = 0.f, p1 = 0.f, p2 = 0.f, p3 = 0.f;
    for (int d = lane; d < din; d += 32) {
        float xv = xr[d];
        p0 += xv * gw[0 * din + d];
        p1 += xv * gw[1 * din + d];
        p2 += xv * gw[2 * din + d];
        p3 += xv * gw[3 * din + d];
    }
    #pragma unroll
    for (int o = 16; o > 0; o >>= 1) {
        p0 += __shfl_xor_sync(0xffffffffu, p0, o);
        p1 += __shfl_xor_sync(0xffffffffu, p1, o);
        p2 += __shfl_xor_sync(0xffffffffu, p2, o);
        p3 += __shfl_xor_sync(0xffffffffu, p3, o);
    }
    if (lane == 0) {
        float sc[4] = { p0 + gb[0], p1 + gb[1], p2 + gb[2], p3 + gb[3] };
        float m = fmaxf(fmaxf(sc[0], sc[1]), fmaxf(sc[2], sc[3]));
        float e[4]; float sum = 0.f;
        #pragma unroll
        for (int i = 0; i < 4; i++) { e[i] = __expf(sc[i] - m); sum += e[i]; }
        float inv = 1.f / sum;
        #pragma unroll
        for (int i = 0; i < 4; i++) e[i] *= inv;
        int i0 = 0;
        #pragma unroll
        for (int i = 1; i < 4; i++) if (e[i] > e[i0]) i0 = i;
        int i1 = -1;
        #pragma unroll
        for (int i = 0; i < 4; i++) {
            if (i == i0) continue;
            if (i1 < 0 || e[i] > e[i1]) i1 = i;
        }
        vals[tok * 2 + 0] = e[i0];
        vals[tok * 2 + 1] = e[i1];
        if (tok == 0) { sel[0] = i0; sel[1] = i1; }
    }
}

// ---------------- MoE combine (dual write, x2 vectorized) ----------------
__global__ void moe_combine(const float* __restrict__ e0, const float* __restrict__ e1,
                            const float* __restrict__ eb, const float* __restrict__ vals,
                            const int* __restrict__ sel, float* __restrict__ out,
                            bf16* __restrict__ outb) {
    long p = (long)blockIdx.x * blockDim.x + threadIdx.x;
    if (p >= (long)S_ * H_ / 2) return;
    long i = p * 2;
    int s = (int)(i / H_);
    int h = (int)(i % H_);
    float2 b0 = *(const float2*)(eb + sel[0] * H_ + h);
    float2 b1 = *(const float2*)(eb + sel[1] * H_ + h);
    float2 a  = *(const float2*)(e0 + i);
    float2 b  = *(const float2*)(e1 + i);
    float v0s = vals[s * 2], v1s = vals[s * 2 + 1];
    float r0 = v0s * (a.x + b0.x) + v1s * (b.x + b1.x);
    float r1 = v0s * (a.y + b0.y) + v1s * (b.y + b1.y);
    *(float2*)(out + i) = make_float2(r0, r1);
    __nv_bfloat162 pk = __float22bfloat162_rn(make_float2(r0, r1));
    *(__nv_bfloat162*)(outb + i) = pk;
}

#define MMA_BF16(ACC, A0, A1, A2, A3, B0, B1)                                  \
    asm volatile(                                                              \
        "mma.sync.aligned.m16n8k16.row.col.f32.bf16.bf16.f32 "                 \
        "{%0,%1,%2,%3}, {%4,%5,%6,%7}, {%8,%9}, {%0,%1,%2,%3};\n"              \
        : "+f"((ACC)[0]), "+f"((ACC)[1]), "+f"((ACC)[2]), "+f"((ACC)[3])       \
        : "r"(A0), "r"(A1), "r"(A2), "r"(A3), "r"(B0), "r"(B1))

static __device__ __forceinline__ unsigned packbf(float x, float y) {
    __nv_bfloat162 p = __float22bfloat162_rn(make_float2(x, y));
    return *(unsigned*)&p;
}

static __device__ __forceinline__ void cp16(unsigned dst, const void* src, int sz) {
    asm volatile("cp.async.ca.shared.global [%0], [%1], 16, %2;\n"
                 :: "r"(dst), "l"(src), "r"(sz));
}

// ---------------- bf16 GEMM, cp.async 3-stage pipeline, BK=64 ----------------
template <int BN>
__global__ __launch_bounds__(256, 2)
void gemm_bf(const bf16* __restrict__ A, const bf16* __restrict__ B,
             const float* __restrict__ bias, float* __restrict__ C, bf16* __restrict__ Cb,
             int M, int N, int K, int lda, int ldb, int ldc,
             long batchC, int do_relu, const int* __restrict__ sel, long selStride) {
    constexpr int BM = 128, BK = 64, PAD = 8;
    constexpr int RS = BK + PAD;
    constexpr int ROWS = BM + BN;
    constexpr int NT = BN / 16;
    extern __shared__ __align__(16) bf16 sm[];

    if (sel) B += (long)sel[blockIdx.z] * selStride;
    long zoff = (long)blockIdx.z * batchC;

    int bm = blockIdx.y * BM;
    int bn = blockIdx.x * BN;
    int tid  = threadIdx.x;
    int lane = tid & 31;
    int wid  = tid >> 5;
    int warpM = (wid & 3) * 32;
    int warpN = (wid >> 2) * (BN / 2);
    unsigned sbase = (unsigned)__cvta_generic_to_shared(sm);

    auto issue = [&](int stage, int k0) {
        #pragma unroll
        for (int t = 0; t < BM * 8 / 256; t++) {
            int idx = tid + t * 256;
            int row = idx >> 3, c = idx & 7;
            const void* src = A + (long)(bm + row) * lda + k0 + c * 8;
            unsigned dst = sbase + (unsigned)(((stage * ROWS + row) * RS + c * 8) * 2);
            cp16(dst, src, 16);
        }
        #pragma unroll
        for (int t = 0; t < BN * 8 / 256; t++) {
            int idx = tid + t * 256;
            int row = idx >> 3, c = idx & 7;
            int gn = bn + row;
            const void* src = B + (long)(gn < N ? gn : 0) * ldb + k0 + c * 8;
            unsigned dst = sbase + (unsigned)(((stage * ROWS + BM + row) * RS + c * 8) * 2);
            cp16(dst, src, gn < N ? 16 : 0);
        }
        asm volatile("cp.async.commit_group;\n");
    };

    float acc[2][NT][4];
    #pragma unroll
    for (int mt = 0; mt < 2; mt++)
        #pragma unroll
        for (int nt = 0; nt < NT; nt++)
            #pragma unroll
            for (int r = 0; r < 4; r++) acc[mt][nt][r] = 0.f;

    int g = lane >> 2;
    int q = lane & 3;
    int ntiles = K / BK;

    auto compute = [&](int stage) {
        const bf16* As = sm + stage * ROWS * RS;
        const bf16* Bs = As + BM * RS;
        #pragma unroll
        for (int ks = 0; ks < BK; ks += 16) {
            unsigned a[2][4], b[NT][2];
            int ac = ks + q * 2;
            #pragma unroll
            for (int mt = 0; mt < 2; mt++) {
                int r = warpM + mt * 16 + g;
                a[mt][0] = *(const unsigned*)&As[r * RS + ac];
                a[mt][1] = *(const unsigned*)&As[(r + 8) * RS + ac];
                a[mt][2] = *(const unsigned*)&As[r * RS + ac + 8];
                a[mt][3] = *(const unsigned*)&As[(r + 8) * RS + ac + 8];
            }
            #pragma unroll
            for (int nt = 0; nt < NT; nt++) {
                int nr = warpN + nt * 8 + g;
                b[nt][0] = *(const unsigned*)&Bs[nr * RS + ac];
                b[nt][1] = *(const unsigned*)&Bs[nr * RS + ac + 8];
            }
            #pragma unroll
            for (int mt = 0; mt < 2; mt++)
                #pragma unroll
                for (int nt = 0; nt < NT; nt++)
                    MMA_BF16(acc[mt][nt], a[mt][0], a[mt][1], a[mt][2], a[mt][3],
                             b[nt][0], b[nt][1]);
        }
    };

    issue(0, 0);
    if (ntiles > 1) issue(1, BK);
    for (int t = 0; t < ntiles; t++) {
        if (t == ntiles - 1)
            asm volatile("cp.async.wait_group 0;\n");
        else
            asm volatile("cp.async.wait_group 1;\n");
        __syncthreads();
        if (t + 2 < ntiles) issue((t + 2) % 3, (t + 2) * BK);
        compute(t % 3);
    }

    #pragma unroll
    for (int mt = 0; mt < 2; mt++) {
        int row0 = bm + warpM + mt * 16 + g;
        #pragma unroll
        for (int nt = 0; nt < NT; nt++) {
            int col = bn + warpN + nt * 8 + q * 2;
            if (col >= N) continue;
            float b0 = bias ? bias[col]     : 0.f;
            float b1 = bias ? bias[col + 1] : 0.f;
            float v00 = acc[mt][nt][0] + b0;
            float v01 = acc[mt][nt][1] + b1;
            float v10 = acc[mt][nt][2] + b0;
            float v11 = acc[mt][nt][3] + b1;
            if (do_relu) {
                v00 = fmaxf(v00, 0.f); v01 = fmaxf(v01, 0.f);
                v10 = fmaxf(v10, 0.f); v11 = fmaxf(v11, 0.f);
            }
            if (Cb) {
                *(unsigned*)(Cb + zoff + (long)row0 * ldc + col)       = packbf(v00, v01);
                *(unsigned*)(Cb + zoff + (long)(row0 + 8) * ldc + col) = packbf(v10, v11);
            } else {
                *(float2*)(C + zoff + (long)row0 * ldc + col)       = make_float2(v00, v01);
                *(float2*)(C + zoff + (long)(row0 + 8) * ldc + col) = make_float2(v10, v11);
            }
        }
    }
}

// ---------------- split-KV flash attention, smem double-buffered K/V ----------------
#define FL_SMEM (128 * 72 + 2 * 64 * 72 + 2 * 64 * 72)
__global__ __launch_bounds__(256)
void flash_attn(const bf16* __restrict__ qkv, float* __restrict__ po,
                float* __restrict__ ml) {
    constexpr int BM = 128, BN = 64, RSF = 72;
    constexpr int JT = S_ / BN / KVSPLIT;
    extern __shared__ __align__(16) bf16 smf[];
    bf16* Qs    = smf;
    bf16* Kbase = smf + 128 * RSF;
    bf16* Vbase = Kbase + 2 * 64 * RSF;

    int h  = blockIdx.y;
    int z  = blockIdx.z;
    int bm = blockIdx.x * BM;
    int tid = threadIdx.x;
    int lane = tid & 31;
    int w = tid >> 5;
    int g = lane >> 2;
    int q = lane & 3;

    const bf16* Qp = qkv + h * HD_;
    const bf16* Kp = qkv + H_ + h * HD_;
    const bf16* Vp = qkv + 2 * H_ + h * HD_;

    int skey[2], sc[2];
    #pragma unroll
    for (int i = 0; i < 2; i++) {
        int idx = tid + i * 256;
        skey[i] = idx >> 3;
        sc[i]   = idx & 7;
    }

    #pragma unroll
    for (int i = 0; i < 4; i++) {
        int idx = tid + i * 256;
        int row = idx >> 3;
        int c   = idx & 7;
        uint4 v = *(const uint4*)(Qp + (long)(bm + row) * (3 * H_) + c * 8);
        *(uint4*)&Qs[row * RSF + c * 8] = v;
    }

    float m0 = -1e30f, m1 = -1e30f, l0 = 0.f, l1 = 0.f;
    float out[8][4];
    #pragma unroll
    for (int ot = 0; ot < 8; ot++)
        #pragma unroll
        for (int r = 0; r < 4; r++) out[ot][r] = 0.f;

    int rowA = w * 16 + g;

    long jbase = (long)z * JT * BN;
    uint4 kreg[2], vreg[2];
    #pragma unroll
    for (int i = 0; i < 2; i++) {
        kreg[i] = *(const uint4*)(Kp + (jbase + skey[i]) * (3 * H_) + sc[i] * 8);
        vreg[i] = *(const uint4*)(Vp + (jbase + skey[i]) * (3 * H_) + sc[i] * 8);
    }

    for (int jj = 0; jj < JT; jj++) {
        bf16* Ks = Kbase + (jj & 1) * 64 * RSF;
        bf16* Vs = Vbase + (jj & 1) * 64 * RSF;
        #pragma unroll
        for (int i = 0; i < 2; i++) {
            *(uint4*)&Ks[skey[i] * RSF + sc[i] * 8] = kreg[i];
            __nv_bfloat162 p0 = *(__nv_bfloat162*)&vreg[i].x;
            __nv_bfloat162 p1 = *(__nv_bfloat162*)&vreg[i].y;
            __nv_bfloat162 p2 = *(__nv_bfloat162*)&vreg[i].z;
            __nv_bfloat162 p3 = *(__nv_bfloat162*)&vreg[i].w;
            int d0 = sc[i] * 8;
            int key = skey[i];
            Vs[(d0 + 0) * RSF + key] = p0.x; Vs[(d0 + 1) * RSF + key] = p0.y;
            Vs[(d0 + 2) * RSF + key] = p1.x; Vs[(d0 + 3) * RSF + key] = p1.y;
            Vs[(d0 + 4) * RSF + key] = p2.x; Vs[(d0 + 5) * RSF + key] = p2.y;
            Vs[(d0 + 6) * RSF + key] = p3.x; Vs[(d0 + 7) * RSF + key] = p3.y;
        }
        __syncthreads();

        if (jj + 1 < JT) {
            long base = jbase + (long)(jj + 1) * BN;
            #pragma unroll
            for (int i = 0; i < 2; i++) {
                kreg[i] = *(const uint4*)(Kp + (base + skey[i]) * (3 * H_) + sc[i] * 8);
                vreg[i] = *(const uint4*)(Vp + (base + skey[i]) * (3 * H_) + sc[i] * 8);
            }
        }

        float acc[8][4];
        #pragma unroll
        for (int nt = 0; nt < 8; nt++)
            #pragma unroll
            for (int r = 0; r < 4; r++) acc[nt][r] = 0.f;
        #pragma unroll
        for (int kc = 0; kc < 4; kc++) {
            int ac = kc * 16 + q * 2;
            unsigned a0 = *(const unsigned*)&Qs[rowA * RSF + ac];
            unsigned a1 = *(const unsigned*)&Qs[(rowA + 8) * RSF + ac];
            unsigned a2 = *(const unsigned*)&Qs[rowA * RSF + ac + 8];
            unsigned a3 = *(const unsigned*)&Qs[(rowA + 8) * RSF + ac + 8];
            #pragma unroll
            for (int nt = 0; nt < 8; nt++) {
                unsigned b0 = *(const unsigned*)&Ks[(nt * 8 + g) * RSF + ac];
                unsigned b1 = *(const unsigned*)&Ks[(nt * 8 + g) * RSF + ac + 8];
                MMA_BF16(acc[nt], a0, a1, a2, a3, b0, b1);
            }
        }

        float tm0 = -1e30f, tm1 = -1e30f;
        #pragma unroll
        for (int nt = 0; nt < 8; nt++) {
            acc[nt][0] *= SCALE_; acc[nt][1] *= SCALE_;
            acc[nt][2] *= SCALE_; acc[nt][3] *= SCALE_;
            tm0 = fmaxf(tm0, fmaxf(acc[nt][0], acc[nt][1]));
            tm1 = fmaxf(tm1, fmaxf(acc[nt][2], acc[nt][3]));
        }
        tm0 = fmaxf(tm0, __shfl_xor_sync(0xffffffffu, tm0, 1));
        tm0 = fmaxf(tm0, __shfl_xor_sync(0xffffffffu, tm0, 2));
        tm1 = fmaxf(tm1, __shfl_xor_sync(0xffffffffu, tm1, 1));
        tm1 = fmaxf(tm1, __shfl_xor_sync(0xffffffffu, tm1, 2));
        float mn0 = fmaxf(m0, tm0), mn1 = fmaxf(m1, tm1);
        float corr0 = __expf(m0 - mn0), corr1 = __expf(m1 - mn1);
        float s0 = 0.f, s1 = 0.f;
        #pragma unroll
        for (int nt = 0; nt < 8; nt++) {
            acc[nt][0] = __expf(acc[nt][0] - mn0);
            acc[nt][1] = __expf(acc[nt][1] - mn0);
            acc[nt][2] = __expf(acc[nt][2] - mn1);
            acc[nt][3] = __expf(acc[nt][3] - mn1);
            s0 += acc[nt][0] + acc[nt][1];
            s1 += acc[nt][2] + acc[nt][3];
        }
        m0 = mn0; m1 = mn1;
        l0 = l0 * corr0 + s0;
        l1 = l1 * corr1 + s1;
        #pragma unroll
        for (int ot = 0; ot < 8; ot++) {
            out[ot][0] *= corr0; out[ot][1] *= corr0;
            out[ot][2] *= corr1; out[ot][3] *= corr1;
        }

        #pragma unroll
        for (int kc = 0; kc < 4; kc++) {
            unsigned a0 = packbf(acc[2 * kc][0],     acc[2 * kc][1]);
            unsigned a1 = packbf(acc[2 * kc][2],     acc[2 * kc][3]);
            unsigned a2 = packbf(acc[2 * kc + 1][0], acc[2 * kc + 1][1]);
            unsigned a3 = packbf(acc[2 * kc + 1][2], acc[2 * kc + 1][3]);
            int kb = kc * 16 + q * 2;
            #pragma unroll
            for (int ot = 0; ot < 8; ot++) {
                unsigned b0 = *(const unsigned*)&Vs[(ot * 8 + g) * RSF + kb];
                unsigned b1 = *(const unsigned*)&Vs[(ot * 8 + g) * RSF + kb + 8];
                MMA_BF16(out[ot], a0, a1, a2, a3, b0, b1);
            }
        }
    }

    l0 += __shfl_xor_sync(0xffffffffu, l0, 1);
    l0 += __shfl_xor_sync(0xffffffffu, l0, 2);
    l1 += __shfl_xor_sync(0xffffffffu, l1, 1);
    l1 += __shfl_xor_sync(0xffffffffu, l1, 2);
    int row0 = bm + w * 16 + g;
    float* dst = po + (long)z * S_ * H_;
    #pragma unroll
    for (int ot = 0; ot < 8; ot++) {
        int col = h * HD_ + ot * 8 + q * 2;
        *(float2*)(dst + (long)row0 * H_ + col)       = make_float2(out[ot][0], out[ot][1]);
        *(float2*)(dst + (long)(row0 + 8) * H_ + col) = make_float2(out[ot][2], out[ot][3]);
    }
    if (q == 0) {
        long mlbase = ((long)z * NH_ + h) * S_;
        ml[(mlbase + row0) * 2 + 0] = m0;
        ml[(mlbase + row0) * 2 + 1] = l0;
        ml[(mlbase + row0 + 8) * 2 + 0] = m1;
        ml[(mlbase + row0 + 8) * 2 + 1] = l1;
    }
}

// ---------------- split-KV merge (x2 vectorized) ----------------
__global__ void attn_merge(const float* __restrict__ po, const float* __restrict__ ml,
                           bf16* __restrict__ o) {
    long p = (long)blockIdx.x * blockDim.x + threadIdx.x;
    if (p >= (long)S_ * H_ / 2) return;
    long i = p * 2;
    int s   = (int)(i / H_);
    int col = (int)(i % H_);
    int h   = col / HD_;
    float mz[KVSPLIT], lz[KVSPLIT];
    float m = -1e30f;
    #pragma unroll
    for (int z = 0; z < KVSPLIT; z++) {
        mz[z] = ml[(((long)z * NH_ + h) * S_ + s) * 2 + 0];
        lz[z] = ml[(((long)z * NH_ + h) * S_ + s) * 2 + 1];
        m = fmaxf(m, mz[z]);
    }
    float n0 = 0.f, n1 = 0.f, den = 0.f;
    #pragma unroll
    for (int z = 0; z < KVSPLIT; z++) {
        float c = __expf(mz[z] - m);
        float2 v = *(const float2*)(po + (long)z * S_ * H_ + i);
        n0 += v.x * c;
        n1 += v.y * c;
        den += lz[z] * c;
    }
    float inv = 1.f / den;
    __nv_bfloat162 pk = __float22bfloat162_rn(make_float2(n0 * inv, n1 * inv));
    *(__nv_bfloat162*)(o + i) = pk;
}

// ---------------- residual add + LayerNorm (warp-shuffle reductions) ----------------
__global__ void ln_kernel(float* __restrict__ h, const float* __restrict__ t,
                          const float* __restrict__ g, const float* __restrict__ b,
                          bf16* __restrict__ hb) {
    __shared__ float ws1[8], ws2[8];
    int s = blockIdx.x;
    int d = threadIdx.x;
    int lane = d & 31;
    int w = d >> 5;
    float v = h[s * H_ + d] + t[s * H_ + d];
    float sum = v;
    #pragma unroll
    for (int o = 16; o > 0; o >>= 1) sum += __shfl_xor_sync(0xffffffffu, sum, o);
    if (lane == 0) ws1[w] = sum;
    __syncthreads();
    float tot = ws1[0] + ws1[1] + ws1[2] + ws1[3] + ws1[4] + ws1[5] + ws1[6] + ws1[7];
    float m = tot * (1.f / H_);
    float c = v - m;
    float s2 = c * c;
    #pragma unroll
    for (int o = 16; o > 0; o >>= 1) s2 += __shfl_xor_sync(0xffffffffu, s2, o);
    if (lane == 0) ws2[w] = s2;
    __syncthreads();
    float tot2 = ws2[0] + ws2[1] + ws2[2] + ws2[3] + ws2[4] + ws2[5] + ws2[6] + ws2[7];
    float var = tot2 * (1.f / H_);
    float r = c * rsqrtf(var + EPS_) * g[d] + b[d];
    h[s * H_ + d]  = r;
    hb[s * H_ + d] = __float2bfloat16_rn(r);
}

// ---------------- final log_softmax: bf16x2 loads, fp32 out ----------------
__global__ void logsoftmax_kernel(const bf16* __restrict__ logits, float* __restrict__ out) {
    __shared__ float red[256];
    const bf16* p = logits + (long)blockIdx.x * V_;
    float* po = out + (long)blockIdx.x * V_;
    int t = threadIdx.x;
    float2 loc[20];                    // pairs: 256 thr x 20 = 5120 >= V/2 = 5000
    float m = -1e30f;
    #pragma unroll
    for (int i = 0; i < 20; i++) {
        int c2 = t + i * 256;
        if (c2 < V_ / 2) {
            __nv_bfloat162 v = *(const __nv_bfloat162*)(p + c2 * 2);
            loc[i] = make_float2(__bfloat162float(v.x), __bfloat162float(v.y));
        } else {
            loc[i] = make_float2(-1e30f, -1e30f);
        }
        m = fmaxf(m, fmaxf(loc[i].x, loc[i].y));
    }
    red[t] = m;
    __syncthreads();
    for (int o = 128; o > 0; o >>= 1) {
        if (t < o) red[t] = fmaxf(red[t], red[t + o]);
        __syncthreads();
    }
    m = red[0];
    __syncthreads();
    float sum = 0.f;
    #pragma unroll
    for (int i = 0; i < 20; i++) {
        int c2 = t + i * 256;
        if (c2 < V_ / 2)
            sum += __expf(loc[i].x - m) + __expf(loc[i].y - m);
    }
    red[t] = sum;
    __syncthreads();
    for (int o = 128; o > 0; o >>= 1) {
        if (t < o) red[t] += red[t + o];
        __syncthreads();
    }
    float lse = m + __logf(red[0]);
    #pragma unroll
    for (int i = 0; i < 20; i++) {
        int c2 = t + i * 256;
        if (c2 < V_ / 2)
            *(float2*)(po + c2 * 2) = make_float2(loc[i].x - lse, loc[i].y - lse);
    }
}

// ---------------- host side ----------------
static inline void gemm(const bf16* A, const bf16* B, const float* bias,
                        float* C, bf16* Cb,
                        int M, int N, int K, int lda, int ldb, int ldc,
                        int relu,
                        int Z = 1, long batchC = 0,
                        const int* sel = nullptr, long selStride = 0) {
    if (N >= 768) {
        constexpr int SMEM128 = 3 * (128 + 128) * 72 * 2;
        cudaFuncSetAttribute(gemm_bf<128>, cudaFuncAttributeMaxDynamicSharedMemorySize,
                             SMEM128);
        dim3 grid((N + 127) / 128, M / 128, Z);
        gemm_bf<128><<<grid, 256, SMEM128>>>(A, B, bias, C, Cb, M, N, K, lda, ldb, ldc,
                                             batchC, relu, sel, selStride);
    } else {
        constexpr int SMEM64 = 3 * (128 + 64) * 72 * 2;
        cudaFuncSetAttribute(gemm_bf<64>, cudaFuncAttributeMaxDynamicSharedMemorySize,
                             SMEM64);
        dim3 grid((N + 63) / 64, M / 128, Z);
        gemm_bf<64><<<grid, 256, SMEM64>>>(A, B, bias, C, Cb, M, N, K, lda, ldb, ldc,
                                           batchC, relu, sel, selStride);
    }
}

extern "C" void kernel_launch(void* const* d_in, const int* in_sizes, int n_in,
                              void* d_out, int out_size) {
    const int*   x         = (const int*)d_in[0];
    const float* emb       = (const float*)d_in[1];
    const float* moe_gw[3] = { (const float*)d_in[2], (const float*)d_in[6], (const float*)d_in[10] };
    const float* moe_gb[3] = { (const float*)d_in[3], (const float*)d_in[7], (const float*)d_in[11] };
    const float* moe_ew[3] = { (const float*)d_in[4], (const float*)d_in[8], (const float*)d_in[12] };
    const float* moe_eb[3] = { (const float*)d_in[5], (const float*)d_in[9], (const float*)d_in[13] };
    const float* attn_in_w  = (const float*)d_in[14];
    const float* attn_in_b  = (const float*)d_in[15];
    const float* attn_out_w = (const float*)d_in[16];
    const float* attn_out_b = (const float*)d_in[17];
    const float* ln1_g = (const float*)d_in[18];
    const float* ln1_b = (const float*)d_in[19];
    const float* ln2_g = (const float*)d_in[20];
    const float* ln2_b = (const float*)d_in[21];
    const float* ff1_w = (const float*)d_in[22];
    const float* ff1_b = (const float*)d_in[23];
    const float* ff2_w = (const float*)d_in[24];
    const float* ff2_b = (const float*)d_in[25];
    const float* fc_w  = (const float*)d_in[26];
    const float* fc_b  = (const float*)d_in[27];
    const float* out_w = (const float*)d_in[28];
    const float* out_b = (const float*)d_in[29];
    float* out = (float*)d_out;

    float *hbuf, *ybuf, *e0, *pob, *mlb, *vals;
    int* sel;
    bf16 *hbf, *ybf, *qkvbf, *abf, *ffbf, *fcbf, *logbf;
    bf16 *w_ain, *w_aout, *w_ff1, *w_ff2, *w_fc, *w_out, *w_m0, *w_m1, *w_m2;
    cudaGetSymbolAddress((void**)&hbuf, g_h);
    cudaGetSymbolAddress((void**)&ybuf, g_y);
    cudaGetSymbolAddress((void**)&e0,   g_e0);
    cudaGetSymbolAddress((void**)&pob,  g_po);
    cudaGetSymbolAddress((void**)&mlb,  g_ml);
    cudaGetSymbolAddress((void**)&vals, g_vals);
    cudaGetSymbolAddress((void**)&sel,  g_sel);
    cudaGetSymbolAddress((void**)&hbf,   g_hbf);
    cudaGetSymbolAddress((void**)&ybf,   g_ybf);
    cudaGetSymbolAddress((void**)&qkvbf, g_qkvbf);
    cudaGetSymbolAddress((void**)&abf,   g_abf);
    cudaGetSymbolAddress((void**)&ffbf,  g_ffbf);
    cudaGetSymbolAddress((void**)&fcbf,  g_fcbf);
    cudaGetSymbolAddress((void**)&logbf, g_logbf);
    cudaGetSymbolAddress((void**)&w_ain,  g_w_attn_in);
    cudaGetSymbolAddress((void**)&w_aout, g_w_attn_out);
    cudaGetSymbolAddress((void**)&w_ff1,  g_w_ff1);
    cudaGetSymbolAddress((void**)&w_ff2,  g_w_ff2);
    cudaGetSymbolAddress((void**)&w_fc,   g_w_fc);
    cudaGetSymbolAddress((void**)&w_out,  g_w_out);
    cudaGetSymbolAddress((void**)&w_m0,   g_w_moe0);
    cudaGetSymbolAddress((void**)&w_m1,   g_w_moe1);
    cudaGetSymbolAddress((void**)&w_m2,   g_w_moe2);

    // 0) weight conversion — one batched launch
    {
        F2BFJobs j;
        const float* srcs[9] = { attn_in_w, attn_out_w, ff1_w, ff2_w, fc_w,
                                 out_w, moe_ew[0], moe_ew[1], moe_ew[2] };
        bf16* dsts[9] = { w_ain, w_aout, w_ff1, w_ff2, w_fc, w_out, w_m0, w_m1, w_m2 };
        int ns[9] = { NL_ * 3 * H_ * H_, NL_ * H_ * H_, NL_ * FF_ * H_, NL_ * H_ * FF_,
                      H_ * H_, V_ * H_, NE_ * H_ * E_, NE_ * H_ * H_, NE_ * H_ * H_ };
        int acc = 0;
        for (int i = 0; i < 9; i++) {
            j.src[i] = srcs[i];
            j.dst[i] = dsts[i];
            j.off4[i] = acc;
            acc += ns[i] / 4;
        }
        j.off4[9] = acc;
        f2bf_multi<<<(acc + 255) / 256, 256>>>(j);
    }

    // 1) embedding gather
    embed_kernel<<<S_, E_>>>(x, emb, hbuf, hbf);

    // 2) three MoE blocks; ping-pong (fp32 + bf16 views)
    const float* moe_in_f[3]  = { hbuf, ybuf, hbuf };
    const bf16*  moe_in_b[3]  = { hbf,  ybf,  hbf  };
    float*       moe_out_f[3] = { ybuf, hbuf, ybuf };
    bf16*        moe_out_b[3] = { ybf,  hbf,  ybf  };
    const bf16*  moe_w[3]     = { w_m0, w_m1, w_m2 };
    int          moe_din[3]   = { E_, H_, H_ };
    for (int i = 0; i < 3; i++) {
        int din = moe_din[i];
        gate_kernel<<<(S_ * 32) / 256, 256>>>(moe_in_f[i], din, moe_gw[i], moe_gb[i], vals, sel);
        gemm(moe_in_b[i], moe_w[i], nullptr, e0, nullptr, S_, H_, din, din, din, H_,
             0, 2, (long)S_ * H_, sel, (long)H_ * din);
        moe_combine<<<(S_ * H_ / 2 + 255) / 256, 256>>>(e0, e0 + (long)S_ * H_, moe_eb[i],
                                                        vals, sel, moe_out_f[i], moe_out_b[i]);
    }
    float* cur  = ybuf;
    bf16*  curb = ybf;

    // 3) transformer layers
    cudaFuncSetAttribute(flash_attn, cudaFuncAttributeMaxDynamicSharedMemorySize,
                         FL_SMEM * 2);
    for (int l = 0; l < NL_; l++) {
        gemm(curb, w_ain + (long)l * 3 * H_ * H_, attn_in_b + (long)l * 3 * H_,
             nullptr, qkvbf, S_, 3 * H_, H_, H_, H_, 3 * H_, 0);
        flash_attn<<<dim3(S_ / 128, NH_, KVSPLIT), 256, FL_SMEM * 2>>>(qkvbf, pob, mlb);
        attn_merge<<<(S_ * H_ / 2 + 255) / 256, 256>>>(pob, mlb, abf);
        gemm(abf, w_aout + (long)l * H_ * H_, attn_out_b + (long)l * H_,
             e0, nullptr, S_, H_, H_, H_, H_, H_, 0);
        ln_kernel<<<S_, H_>>>(cur, e0, ln1_g + l * H_, ln1_b + l * H_, curb);
        gemm(curb, w_ff1 + (long)l * FF_ * H_, ff1_b + (long)l * FF_,
             nullptr, ffbf, S_, FF_, H_, H_, H_, FF_, 1);
        gemm(ffbf, w_ff2 + (long)l * H_ * FF_, ff2_b + (long)l * H_,
             e0, nullptr, S_, H_, FF_, FF_, FF_, H_, 0);
        ln_kernel<<<S_, H_>>>(cur, e0, ln2_g + l * H_, ln2_b + l * H_, curb);
    }

    // 4) fc + vocab logits (bf16) + log_softmax (bf16 -> fp32 out)
    gemm(curb, w_fc, fc_b, nullptr, fcbf, S_, H_, H_, H_, H_, H_, 0);
    gemm(fcbf, w_out, out_b, nullptr, logbf, S_, V_, H_, H_, H_, V_, 0);
    logsoftmax_kernel<<<S_, 256>>>(logbf, out);
}